// round 6
// baseline (speedup 1.0000x reference)
#include <cuda_runtime.h>
#include <cuda_fp16.h>
#include <cstdint>
#include <math.h>

#define NN 8192
#define IN_F 128
#define OUT_F 64
#define ALPHA 0.2f
#define LOG2E 1.4426950408889634f
#define NCH 64           // chunks of 32 cols over a 2048-col quarter
#define SBCH 8           // chunks per superblock (256 cols)
#define BPITCH 528       // smem row pitch (512B data + 16B) -> 4-bank rotation
#define BBYTES (64 * BPITCH)

// ---------------- device scratch (allocation-free rule) ----------------
__device__ float  g_s1[NN];
__device__ float  g_s2[NN];
__device__ float  g_M;
__device__ __half g_hT[(size_t)OUT_F * NN];     // H^T fp16, [f][j]
__device__ float  g_num[(size_t)4 * NN * OUT_F];
__device__ float  g_den[4 * NN];

// ---------------------------------------------------------------------------
// Kernel A: h = feat @ W^T ; s1/s2 row scores ; g_hT = fp16(h)^T
// ---------------------------------------------------------------------------
__global__ __launch_bounds__(1024) void k_proj(const float* __restrict__ feat,
                                               const float* __restrict__ W,
                                               const float* __restrict__ a) {
    __shared__ float Ws[OUT_F][IN_F + 4];
    __shared__ float Fs[16][IN_F];
    __shared__ float red1[32], red2[32];
    __shared__ __half Ts[OUT_F][18];

    int tid = threadIdx.x;
    int i0  = blockIdx.x * 16;

    for (int t = tid; t < OUT_F * IN_F; t += 1024)
        Ws[t / IN_F][t % IN_F] = W[t];
    for (int t = tid; t < 16 * IN_F; t += 1024)
        Fs[t / IN_F][t % IN_F] = feat[(size_t)(i0 + t / IN_F) * IN_F + (t % IN_F)];
    __syncthreads();

    int f = tid & 63;
    int r = tid >> 6;
    float acc = 0.f;
#pragma unroll
    for (int k = 0; k < IN_F; k += 4) {
        float4 fv = *(const float4*)&Fs[r][k];
        float4 wv = *(const float4*)&Ws[f][k];
        acc += fv.x * wv.x + fv.y * wv.y + fv.z * wv.z + fv.w * wv.w;
    }

    Ts[f][r] = __float2half(acc);

    float t1 = acc * a[f];
    float t2 = acc * a[OUT_F + f];
#pragma unroll
    for (int off = 16; off; off >>= 1) {
        t1 += __shfl_xor_sync(0xffffffffu, t1, off);
        t2 += __shfl_xor_sync(0xffffffffu, t2, off);
    }
    int w = tid >> 5;
    if ((tid & 31) == 0) { red1[w] = t1; red2[w] = t2; }
    __syncthreads();
    if (tid < 16) {
        g_s1[i0 + tid] = red1[2 * tid] + red1[2 * tid + 1];
        g_s2[i0 + tid] = red2[2 * tid] + red2[2 * tid + 1];
    }
    if (tid < 512) {
        int ff = tid >> 3, u = tid & 7;
        __half2 pk = __halves2half2(Ts[ff][2 * u], Ts[ff][2 * u + 1]);
        *(__half2*)&g_hT[(size_t)ff * NN + i0 + 2 * u] = pk;
    }
}

// ---------------------------------------------------------------------------
// Kernel B: g_M = max_j s2[j]
// ---------------------------------------------------------------------------
__global__ __launch_bounds__(256) void k_max() {
    __shared__ float red[8];
    int tid = threadIdx.x;
    float m = -1e30f;
    for (int i = tid; i < NN; i += 256) m = fmaxf(m, g_s2[i]);
#pragma unroll
    for (int off = 16; off; off >>= 1)
        m = fmaxf(m, __shfl_xor_sync(0xffffffffu, m, off));
    if ((tid & 31) == 0) red[tid >> 5] = m;
    __syncthreads();
    if (tid == 0) {
        float mm = red[0];
#pragma unroll
        for (int i = 1; i < 8; i++) mm = fmaxf(mm, red[i]);
        g_M = mm;
    }
}

// ---------------------------------------------------------------------------
// Main fused kernel. 256 CTAs = 64 row-tiles(128 rows) x 4 K-quarters.
// 2 CTAs/SM (4 warps/SMSP). Adjacency combined + log2e-scaled at load time.
// ---------------------------------------------------------------------------
struct AdjRegs {
    float2 C[2][2][2];   // (geo+sem)*log2e  [row(r / r+8)][kk][chalf]
    float2 Z[2][2];      // s2 [kk][chalf]
};

__device__ __forceinline__ void load_chunk(const float* __restrict__ gp0,
                                           const float* __restrict__ sp0,
                                           const float* __restrict__ s2p,
                                           int c, AdjRegs& A) {
    size_t off = (size_t)c * 32;
#pragma unroll
    for (int ro = 0; ro < 2; ro++)
#pragma unroll
        for (int kk = 0; kk < 2; kk++)
#pragma unroll
            for (int ch = 0; ch < 2; ch++) {
                size_t o = off + (size_t)ro * 8 * NN + kk * 16 + ch * 8;
                float2 g = __ldcs((const float2*)(gp0 + o));
                float2 s = __ldcs((const float2*)(sp0 + o));
                A.C[ro][kk][ch] = make_float2((g.x + s.x) * LOG2E,
                                              (g.y + s.y) * LOG2E);
            }
#pragma unroll
    for (int kk = 0; kk < 2; kk++)
#pragma unroll
        for (int ch = 0; ch < 2; ch++)
            A.Z[kk][ch] = *(const float2*)(s2p + off + kk * 16 + ch * 8);
}

__device__ __forceinline__ void mma16816(float* d, const uint32_t* a,
                                         uint32_t b0, uint32_t b1) {
    asm volatile(
        "mma.sync.aligned.m16n8k16.row.col.f32.f16.f16.f32 "
        "{%0,%1,%2,%3},{%4,%5,%6,%7},{%8,%9},{%0,%1,%2,%3};"
        : "+f"(d[0]), "+f"(d[1]), "+f"(d[2]), "+f"(d[3])
        : "r"(a[0]), "r"(a[1]), "r"(a[2]), "r"(a[3]), "r"(b0), "r"(b1));
}

__device__ __forceinline__ void proc_chunk(int c, AdjRegs& cur, AdjRegs& nxt,
                                           const float* gp0, const float* sp0,
                                           const float* s2p, uint32_t ldb,
                                           float s10, float s11, float bn0, float bn1,
                                           float (&dloc)[2], float (&acc)[8][4]) {
    // 1. prefetch next chunk's adjacency (in flight across whole chunk)
    int cn = (c + 1 < NCH) ? c + 1 : 0;
    load_chunk(gp0, sp0, s2p, cn, nxt);

    // 2. compute P in A-fragment layout; per-chunk den in half2
    uint32_t af[2][4];
    __half2 dh[2];
    dh[0] = __float2half2_rn(0.f);
    dh[1] = dh[0];
#pragma unroll
    for (int kk = 0; kk < 2; kk++)
#pragma unroll
        for (int ch = 0; ch < 2; ch++)
#pragma unroll
            for (int ro = 0; ro < 2; ro++) {
                float2 cl = cur.C[ro][kk][ch];
                float s1 = ro ? s11 : s10;
                float bn = ro ? bn1 : bn0;
                float xx = s1 + cur.Z[kk][ch].x;
                float xy = s1 + cur.Z[kk][ch].y;
                float lx = fmaxf(xx, ALPHA * xx);
                float ly = fmaxf(xy, ALPHA * xy);
                float px = (cl.x > 0.f) ? exp2f(fmaf(lx, cl.x, -bn)) : 0.f;
                float py = (cl.y > 0.f) ? exp2f(fmaf(ly, cl.y, -bn)) : 0.f;
                __half2 ph = __floats2half2_rn(px, py);
                dh[ro] = __hadd2(dh[ro], ph);      // sums the SAME rounded halves
                af[kk][ro + 2 * ch] = *(uint32_t*)&ph;
            }
#pragma unroll
    for (int ro = 0; ro < 2; ro++) {
        float2 df = __half22float2(dh[ro]);
        dloc[ro] += df.x + df.y;
    }

    // 3. B-frags from superblock buffer (no sync), 16 mma
    uint32_t base = ldb + (uint32_t)(c & (SBCH - 1)) * 64;
#pragma unroll
    for (int kk = 0; kk < 2; kk++) {
#pragma unroll
        for (int t = 0; t < 4; t++) {
            uint32_t b0, b1, b2, b3;
            uint32_t ad = base + t * (16 * BPITCH) + kk * 32;
            asm volatile(
                "ldmatrix.sync.aligned.m8n8.x4.shared.b16 {%0,%1,%2,%3}, [%4];"
                : "=r"(b0), "=r"(b1), "=r"(b2), "=r"(b3) : "r"(ad));
            mma16816(acc[2 * t],     af[kk], b0, b1);
            mma16816(acc[2 * t + 1], af[kk], b2, b3);
        }
    }
}

__global__ __launch_bounds__(256, 2) void k_main(const float* __restrict__ geo,
                                                 const float* __restrict__ sem) {
    extern __shared__ __align__(16) char Bbuf[];   // 2 x 64 rows x 528B

    int tid = threadIdx.x, lane = tid & 31, w = tid >> 5;
    int r = lane >> 2, tg = lane & 3;
    int rb = blockIdx.x >> 2, q = blockIdx.x & 3;
    int i0 = rb * 128, jbase = q * 2048;

    int row0 = i0 + 16 * w + r;
    const float* gp0 = geo + (size_t)row0 * NN + jbase + 2 * tg;
    const float* sp0 = sem + (size_t)row0 * NN + jbase + 2 * tg;
    const float* s2p = g_s2 + jbase + 2 * tg;

    float Mv  = g_M;
    float s10 = g_s1[row0], s11 = g_s1[row0 + 8];
    float bn0 = fmaxf(0.f, 2.f * (s10 + Mv)) * LOG2E;
    float bn1 = fmaxf(0.f, 2.f * (s11 + Mv)) * LOG2E;

    uint32_t smem0;
    asm("{ .reg .u64 t; cvta.to.shared.u64 t, %1; cvt.u32.u64 %0, t; }"
        : "=r"(smem0) : "l"(Bbuf));

    // cp.async staging map: thread covers rows (tid>>5)+8p, 16B segment tid&31
    int srow = tid >> 5, sseg = tid & 31;
    const __half* gsrc0 = g_hT + (size_t)srow * NN + jbase + sseg * 8;
    uint32_t sdst0 = smem0 + srow * BPITCH + sseg * 16;

    // ldmatrix per-lane base
    int ldrow = ((lane >> 4) & 1) * 8 + (lane & 7);
    int ldcol = ((lane >> 3) & 1) * 16;
    uint32_t ldb0 = smem0 + ldrow * BPITCH + ldcol;

    float acc[8][4];
#pragma unroll
    for (int i = 0; i < 8; i++)
#pragma unroll
        for (int j = 0; j < 4; j++) acc[i][j] = 0.f;
    float dloc[2] = {0.f, 0.f};

    // prologue: stage superblock 0
#pragma unroll
    for (int p = 0; p < 8; p++) {
        const __half* gp = gsrc0 + (size_t)(8 * p) * NN;
        uint32_t sd = sdst0 + 8 * p * BPITCH;
        asm volatile("cp.async.cg.shared.global [%0], [%1], 16;" :: "r"(sd), "l"(gp));
    }
    asm volatile("cp.async.commit_group;");
    asm volatile("cp.async.wait_group 0;");

    AdjRegs A0, A1;
    load_chunk(gp0, sp0, s2p, 0, A0);
    __syncthreads();

    int c = 0;
    for (int sb = 0; sb < NCH / SBCH; sb++) {
        if (sb + 1 < NCH / SBCH) {
            int jblk = (sb + 1) * (SBCH * 32);
            uint32_t sd0 = sdst0 + ((sb + 1) & 1) * BBYTES;
#pragma unroll
            for (int p = 0; p < 8; p++) {
                const __half* gp = gsrc0 + (size_t)(8 * p) * NN + jblk;
                asm volatile("cp.async.cg.shared.global [%0], [%1], 16;"
                             :: "r"(sd0 + 8 * p * BPITCH), "l"(gp));
            }
            asm volatile("cp.async.commit_group;");
        }

        uint32_t ldb = ldb0 + (sb & 1) * BBYTES;
#pragma unroll 2
        for (int cc = 0; cc < SBCH; cc += 2) {
            proc_chunk(c,     A0, A1, gp0, sp0, s2p, ldb, s10, s11, bn0, bn1, dloc, acc);
            proc_chunk(c + 1, A1, A0, gp0, sp0, s2p, ldb, s10, s11, bn0, bn1, dloc, acc);
            c += 2;
        }

        asm volatile("cp.async.wait_group 0;");
        __syncthreads();
    }

    // denominators: reduce over the 4 lanes of each row-quad
#pragma unroll
    for (int ro = 0; ro < 2; ro++) {
        float v = dloc[ro];
        v += __shfl_xor_sync(0xffffffffu, v, 1);
        v += __shfl_xor_sync(0xffffffffu, v, 2);
        dloc[ro] = v;
    }
    if (tg == 0) {
        g_den[q * NN + row0]     = dloc[0];
        g_den[q * NN + row0 + 8] = dloc[1];
    }

    // numerator partials: c-frag layout -> float2 stores
    float* dst0 = g_num + ((size_t)q * NN + row0) * OUT_F;
    float* dst1 = g_num + ((size_t)q * NN + row0 + 8) * OUT_F;
#pragma unroll
    for (int t = 0; t < 8; t++) {
        int n0 = 8 * t + 2 * tg;
        *(float2*)(dst0 + n0) = make_float2(acc[t][0], acc[t][1]);
        *(float2*)(dst1 + n0) = make_float2(acc[t][2], acc[t][3]);
    }
}

// ---------------------------------------------------------------------------
// Combine split-K partials: out = elu(sum(n)/sum(d))
// ---------------------------------------------------------------------------
__global__ __launch_bounds__(256) void k_fin(float* __restrict__ out) {
    int idx = blockIdx.x * 256 + threadIdx.x;
    int row = idx >> 4, qq = idx & 15;
    float den = g_den[row] + g_den[NN + row] + g_den[2 * NN + row] + g_den[3 * NN + row];
    float inv = 1.0f / den;
    float4 n0 = *(const float4*)&g_num[(size_t)row * OUT_F + 4 * qq];
    float4 n1 = *(const float4*)&g_num[(size_t)(NN + row) * OUT_F + 4 * qq];
    float4 n2 = *(const float4*)&g_num[(size_t)(2 * NN + row) * OUT_F + 4 * qq];
    float4 n3 = *(const float4*)&g_num[(size_t)(3 * NN + row) * OUT_F + 4 * qq];
    float4 o;
    float v;
    v = (n0.x + n1.x + n2.x + n3.x) * inv; o.x = (v > 0.f) ? v : expm1f(v);
    v = (n0.y + n1.y + n2.y + n3.y) * inv; o.y = (v > 0.f) ? v : expm1f(v);
    v = (n0.z + n1.z + n2.z + n3.z) * inv; o.z = (v > 0.f) ? v : expm1f(v);
    v = (n0.w + n1.w + n2.w + n3.w) * inv; o.w = (v > 0.f) ? v : expm1f(v);
    *(float4*)&out[(size_t)row * OUT_F + 4 * qq] = o;
}

// ---------------------------------------------------------------------------
extern "C" void kernel_launch(void* const* d_in, const int* in_sizes, int n_in,
                              void* d_out, int out_size) {
    const float* geo  = (const float*)d_in[0];
    const float* sem  = (const float*)d_in[1];
    const float* feat = (const float*)d_in[2];
    const float* W    = (const float*)d_in[3];
    const float* a    = (const float*)d_in[4];
    float* out = (float*)d_out;

    const int DYN = 2 * BBYTES;   // 67,584 B -> 2 CTAs/SM
    cudaFuncSetAttribute(k_main, cudaFuncAttributeMaxDynamicSharedMemorySize, DYN);

    k_proj<<<NN / 16, 1024>>>(feat, W, a);
    k_max<<<1, 256>>>();
    k_main<<<256, 256, DYN>>>(geo, sem);
    k_fin<<<512, 256>>>(out);
}